// round 4
// baseline (speedup 1.0000x reference)
#include <cuda_runtime.h>
#include <cstdint>

#define BB   32
#define TT   1024
#define HID  512
#define G4   2048            // 4*HID
#define MROWS (BB*TT)        // 32768
#define NCTA 128
#define OUT_MAIN (BB*TT*HID) // 16777216

typedef unsigned long long ull;

__device__ __forceinline__ ull pack2(float x) {
    ull d; asm("mov.b64 %0, {%1, %1};" : "=l"(d) : "f"(x)); return d;
}
__device__ __forceinline__ ull fma2(ull a, ull b, ull c) {
    ull d; asm("fma.rn.f32x2 %0, %1, %2, %3;" : "=l"(d) : "l"(a), "l"(b), "l"(c)); return d;
}
__device__ __forceinline__ void unpack2(ull v, float& lo, float& hi) {
    asm("mov.b64 {%0, %1}, %2;" : "=f"(lo), "=f"(hi) : "l"(v));
}

// -------------------- device scratch --------------------
__device__ float g_G[(size_t)MROWS * G4];           // precomputed input-side gates
__device__ float g_Y0[(size_t)(TT + 1) * BB * HID]; // layer-0 hidden outputs (slot t+1 = h_t)
__device__ unsigned g_bar[2];

__global__ void init_kernel() {
    if (threadIdx.x < 2) g_bar[threadIdx.x] = 0u;
}

// -------------------- big GEMM (FFMA2) --------------------
template <int MODE>
__global__ __launch_bounds__(256) void gemm_kernel(
    const float* __restrict__ A,
    const float* __restrict__ W,
    const float* __restrict__ bih,
    const float* __restrict__ bhh,
    float* __restrict__ Gout)
{
    __shared__ float As[16 * 132];
    __shared__ float Bs[16 * 66];

    const int tid = threadIdx.x;
    const int bm = blockIdx.y;
    const int bn = blockIdx.x;
    const int ty = tid >> 4;
    const int tx = tid & 15;

    ull acc2[8][2];
#pragma unroll
    for (int i = 0; i < 8; i++) { acc2[i][0] = 0ULL; acc2[i][1] = 0ULL; }

    for (int kt = 0; kt < HID; kt += 16) {
#pragma unroll
        for (int q = 0; q < 2; q++) {
            int idx = tid + q * 256;
            int lrow = idx >> 2;
            int lk = (idx & 3) << 2;
            int r = bm * 128 + lrow;
            const float* ap;
            if (MODE == 0)
                ap = A + ((size_t)(r & 31) * TT + (size_t)(r >> 5)) * HID;
            else
                ap = A + (size_t)r * HID;
            float4 v = *(const float4*)(ap + kt + lk);
            As[(lk + 0) * 132 + lrow] = v.x;
            As[(lk + 1) * 132 + lrow] = v.y;
            As[(lk + 2) * 132 + lrow] = v.z;
            As[(lk + 3) * 132 + lrow] = v.w;
        }
        {
            int ln = tid >> 2;
            int lk = (tid & 3) << 2;
            float4 v = *(const float4*)(W + (size_t)(bn * 64 + ln) * HID + kt + lk);
            Bs[(lk + 0) * 66 + ln] = v.x;
            Bs[(lk + 1) * 66 + ln] = v.y;
            Bs[(lk + 2) * 66 + ln] = v.z;
            Bs[(lk + 3) * 66 + ln] = v.w;
        }
        __syncthreads();

#pragma unroll
        for (int k = 0; k < 16; k++) {
            float4 a0 = *(const float4*)&As[k * 132 + 4 * ty];
            float4 a1 = *(const float4*)&As[k * 132 + 64 + 4 * ty];
            ull bp0 = *(const ull*)&Bs[k * 66 + 2 * tx];
            ull bp1 = *(const ull*)&Bs[k * 66 + 32 + 2 * tx];
            float av[8] = {a0.x, a0.y, a0.z, a0.w, a1.x, a1.y, a1.z, a1.w};
#pragma unroll
            for (int i = 0; i < 8; i++) {
                ull ad = pack2(av[i]);
                acc2[i][0] = fma2(ad, bp0, acc2[i][0]);
                acc2[i][1] = fma2(ad, bp1, acc2[i][1]);
            }
        }
        __syncthreads();
    }

    int c0 = bn * 64 + 2 * tx;
    int c1 = c0 + 32;
    float bias00 = bih[c0] + bhh[c0];
    float bias01 = bih[c0 + 1] + bhh[c0 + 1];
    float bias10 = bih[c1] + bhh[c1];
    float bias11 = bih[c1 + 1] + bhh[c1 + 1];
#pragma unroll
    for (int i = 0; i < 8; i++) {
        int m = (i < 4) ? (4 * ty + i) : (64 + 4 * ty + i - 4);
        size_t r = (size_t)(bm * 128 + m);
        float x, y;
        unpack2(acc2[i][0], x, y);
        *(float2*)(Gout + r * G4 + c0) = make_float2(x + bias00, y + bias01);
        unpack2(acc2[i][1], x, y);
        *(float2*)(Gout + r * G4 + c1) = make_float2(x + bias10, y + bias11);
    }
}

// -------------------- persistent recurrence kernel --------------------
// Smem layout (bytes from base):
//   w2   : ull [512][16]  (dup weight pairs)        @ 0        (65536)
//   h2   : ull [512][18]  (batch-pair h, pad 18)    @ 65536    (73728)
//   red  : float [16*288]                            @ 139264  (18432)
//   gates: float [512]                               @ 157696  (2048)
//   c_s  : float [128]                               @ 159744  (512)
//   hseg : float [128]                               @ 160256  (512)
#define SM_W2    0
#define SM_H2    65536
#define SM_RED   139264
#define SM_GATES 157696
#define SM_C     159744
#define SM_HSEG  160256
#define SM_TOTAL 160768

__global__ __launch_bounds__(256, 1) void recur_kernel(
    int layer,
    const float* __restrict__ Whh,
    const float* __restrict__ h0l,
    const float* __restrict__ c0l,
    float* __restrict__ out)
{
    extern __shared__ char smraw[];
    ull*   w2      = (ull*)(smraw + SM_W2);
    ull*   h2      = (ull*)(smraw + SM_H2);
    float* h2f     = (float*)(smraw + SM_H2);   // float view, row stride 36
    float* red     = (float*)(smraw + SM_RED);
    float* gates_s = (float*)(smraw + SM_GATES);
    float* c_s     = (float*)(smraw + SM_C);
    float* hseg    = (float*)(smraw + SM_HSEG);

    const int tid = threadIdx.x;
    const int cta = blockIdx.x;
    const int j0 = cta * 4;

    // ---- build duplicated weight pairs w2[k][g] = (w,w), one time ----
    {
        int g = tid >> 4;                      // 0..15
        int type = g >> 2, u = g & 3;
        const float* wr = Whh + (size_t)(type * HID + j0 + u) * HID;
        int k0 = (tid & 15) * 32;
#pragma unroll 8
        for (int kk = 0; kk < 32; kk++)
            w2[(k0 + kk) * 16 + g] = pack2(wr[k0 + kk]);
    }
    if (tid < 128) {
        int b = tid & 31, u = tid >> 5;
        c_s[u * 32 + b] = c0l[(size_t)b * HID + j0 + u];
    }
    __syncthreads();

    const int wid  = tid >> 5;                 // 0..7 = kpos
    const int lane = tid & 31;
    const int gpos = lane >> 3;                // 0..3
    const int bpos = lane & 7;                 // 0..7
    const int g0 = gpos * 4;
    const int kbase = wid * 64;

    // reduce-phase output mapping (512 outputs, 2 per thread)
    const int o0 = tid, o1 = tid + 256;
    const int ga0 = o0 >> 5, ba0 = o0 & 31;
    const int ga1 = o1 >> 5, ba1 = o1 & 31;
    const size_t gcol0 = (size_t)(ga0 >> 2) * HID + j0 + (ga0 & 3);
    const size_t gcol1 = (size_t)(ga1 >> 2) * HID + j0 + (ga1 & 3);
    const int rb0 = ((ga0 & 3) * 4 + (ba0 & 3)) * 288 + (((ba0 >> 2) * 4 + (ga0 >> 2)) * 9);
    const int rb1 = ((ga1 & 3) * 4 + (ba1 & 3)) * 288 + (((ba1 >> 2) * 4 + (ga1 >> 2)) * 9);

    float* out_h_sec = out + OUT_MAIN;
    float* out_c_sec = out + OUT_MAIN + 2 * BB * HID;

    const char* w2c = (const char*)w2 + g0 * 8;       // +k*128
    const char* h2c = (const char*)h2 + bpos * 16;    // +k*144

    for (int t = 0; t < TT; t++) {
        // ---- source of h_{t-1} ----
        const float* src;
        size_t rstride;
        if (layer == 0) {
            src = (t == 0) ? h0l : (g_Y0 + (size_t)t * BB * HID);
            rstride = HID;
        } else {
            if (t == 0) { src = h0l; rstride = HID; }
            else { src = out + (size_t)(t - 1) * HID; rstride = (size_t)TT * HID; }
        }

        // prefetch input-side gates (DRAM, consumed in reduce phase)
        float Gv0 = g_G[(size_t)(t * BB + ba0) * G4 + gcol0];
        float Gv1 = g_G[(size_t)(t * BB + ba1) * G4 + gcol1];

        // ---- per-warp staging: lane = batch, warp's own k-slice [kbase,kbase+64) ----
        {
            const float* srcb = src + (size_t)lane * rstride + kbase;
#pragma unroll
            for (int q = 0; q < 16; q++) {
                float4 v = *(const float4*)(srcb + q * 4);
                int k = kbase + q * 4;
                h2f[(k + 0) * 36 + lane] = v.x;
                h2f[(k + 1) * 36 + lane] = v.y;
                h2f[(k + 2) * 36 + lane] = v.z;
                h2f[(k + 3) * 36 + lane] = v.w;
            }
        }
        __syncwarp();

        // ---- mainloop: acc[p][g]  p = batch pair (2bpos + p), g = g0+j ----
        ull acc[2][4];
#pragma unroll
        for (int p = 0; p < 2; p++)
#pragma unroll
            for (int j = 0; j < 4; j++) acc[p][j] = 0ULL;

#pragma unroll 8
        for (int kk = 0; kk < 64; kk++) {
            int k = kbase + kk;
            ulonglong2 w01 = *(const ulonglong2*)(w2c + (size_t)k * 128);
            ulonglong2 w23 = *(const ulonglong2*)(w2c + (size_t)k * 128 + 16);
            ulonglong2 hp  = *(const ulonglong2*)(h2c + (size_t)k * 144);
            acc[0][0] = fma2(hp.x, w01.x, acc[0][0]);
            acc[0][1] = fma2(hp.x, w01.y, acc[0][1]);
            acc[0][2] = fma2(hp.x, w23.x, acc[0][2]);
            acc[0][3] = fma2(hp.x, w23.y, acc[0][3]);
            acc[1][0] = fma2(hp.y, w01.x, acc[1][0]);
            acc[1][1] = fma2(hp.y, w01.y, acc[1][1]);
            acc[1][2] = fma2(hp.y, w23.x, acc[1][2]);
            acc[1][3] = fma2(hp.y, w23.y, acc[1][3]);
        }

        // ---- write k-split partials, conflict-free (stride 9, coprime 32) ----
        // storage idx = (j*4+i)*288 + (bpos*4+gpos)*9 + kpos
        {
            int Lbase = (bpos * 4 + gpos) * 9 + wid;
#pragma unroll
            for (int p = 0; p < 2; p++) {
#pragma unroll
                for (int j = 0; j < 4; j++) {
                    float lo, hi;
                    unpack2(acc[p][j], lo, hi);
                    int i_lo = 2 * p;          // b = 4*bpos + 2p (+1)
                    red[(j * 4 + i_lo) * 288 + Lbase] = lo;
                    red[(j * 4 + i_lo + 1) * 288 + Lbase] = hi;
                }
            }
        }
        __syncthreads();

        // ---- reduce 8 partials + input-side gates ----
        {
            float s0 = Gv0, s1 = Gv1;
#pragma unroll
            for (int kp = 0; kp < 8; kp++) s0 += red[rb0 + kp];
#pragma unroll
            for (int kp = 0; kp < 8; kp++) s1 += red[rb1 + kp];
            gates_s[o0] = s0;
            gates_s[o1] = s1;
        }
        __syncthreads();

        // ---- activations + state update ----
        if (tid < 128) {
            int b = tid & 31, u = tid >> 5;
            float xi = gates_s[(0 + u) * 32 + b];
            float xf = gates_s[(4 + u) * 32 + b];
            float xg = gates_s[(8 + u) * 32 + b];
            float xo = gates_s[(12 + u) * 32 + b];
            float iv = 1.f / (1.f + __expf(-xi));
            float fv = 1.f / (1.f + __expf(-xf));
            float gv = 1.f - 2.f / (__expf(2.f * xg) + 1.f);
            float ov = 1.f / (1.f + __expf(-xo));
            float c = fv * c_s[u * 32 + b] + iv * gv;
            c_s[u * 32 + b] = c;
            float tc = 1.f - 2.f / (__expf(2.f * c) + 1.f);
            hseg[u * 32 + b] = ov * tc;
        }
        __syncthreads();

        // ---- warp0 publishes h (one STG.128 per batch) + signals ----
        if (tid < 32) {
            int b = tid;
            float4 hv = make_float4(hseg[b], hseg[32 + b], hseg[64 + b], hseg[96 + b]);
            if (layer == 0) {
                *(float4*)(g_Y0 + (size_t)((t + 1) * BB + b) * HID + j0) = hv;
            } else {
                *(float4*)(out + ((size_t)b * TT + t) * HID + j0) = hv;
            }
            if (t == TT - 1) {
                float4 cv = make_float4(c_s[b], c_s[32 + b], c_s[64 + b], c_s[96 + b]);
                *(float4*)(out_h_sec + (size_t)(layer * BB + b) * HID + j0) = hv;
                *(float4*)(out_c_sec + (size_t)(layer * BB + b) * HID + j0) = cv;
            }
            __syncwarp();
            if (tid == 0) {
                asm volatile("fence.acq_rel.gpu;" ::: "memory");
                atomicAdd(&g_bar[layer], 1u);
                unsigned target = (unsigned)(t + 1) * NCTA;
                unsigned v;
                do {
                    asm volatile("ld.relaxed.gpu.global.u32 %0, [%1];"
                                 : "=r"(v) : "l"(&g_bar[layer]));
                    if (v >= target) break;
                    __nanosleep(32);
                } while (true);
                asm volatile("fence.acq_rel.gpu;" ::: "memory");
            }
        }
        __syncthreads();
    }
}

// -------------------- launch --------------------
extern "C" void kernel_launch(void* const* d_in, const int* in_sizes, int n_in,
                              void* d_out, int out_size) {
    const float* input = (const float*)d_in[0];
    const float* h0    = (const float*)d_in[1];
    const float* c0    = (const float*)d_in[2];
    const float* W_ih  = (const float*)d_in[3];
    const float* W_hh  = (const float*)d_in[4];
    const float* b_ih  = (const float*)d_in[5];
    const float* b_hh  = (const float*)d_in[6];
    float* out = (float*)d_out;

    cudaFuncSetAttribute(recur_kernel, cudaFuncAttributeMaxDynamicSharedMemorySize, SM_TOTAL);

    float* Gptr;
    cudaGetSymbolAddress((void**)&Gptr, g_G);
    float* Y0ptr;
    cudaGetSymbolAddress((void**)&Y0ptr, g_Y0);

    init_kernel<<<1, 32>>>();

    dim3 ggrid(32, 256);

    // Layer 0
    gemm_kernel<0><<<ggrid, 256>>>(input, W_ih, b_ih, b_hh, Gptr);
    recur_kernel<<<NCTA, 256, SM_TOTAL>>>(0, W_hh, h0, c0, out);

    // Layer 1 (input = layer-0 outputs; Y0 slots 1..1024 are contiguous rows r+32)
    gemm_kernel<1><<<ggrid, 256>>>(Y0ptr + BB * HID, W_ih + (size_t)G4 * HID,
                                   b_ih + G4, b_hh + G4, Gptr);
    recur_kernel<<<NCTA, 256, SM_TOTAL>>>(1, W_hh + (size_t)G4 * HID,
                                          h0 + BB * HID, c0 + BB * HID, out);
}